// round 13
// baseline (speedup 1.0000x reference)
#include <cuda_runtime.h>
#include <cuda_bf16.h>
#include <cuda_fp16.h>
#include <cstdint>

#define B_   2
#define N_   4096
#define INF_ 256
#define H_   4
#define F_   64
#define BN_  (B_ * N_)      // 8192
#define HF_  (H_ * F_)      // 256
#define MAXD   512
#define MAXD_S 128          // smem capacity (deg mean ~82, P(>128)~1e-7; tail fallback correct)
#define PSTR   (MAXD_S + 4) // 132: bank-shift -> conflict-free float4 LDS

#define GEMM_BLOCKS 256     // (BN_/GBM) * (HF_/GBN) = 64*4
#define CSR_BLOCKS  (N_ / 2)  // 2 adjacency rows per block

// ---------------- scratch (device globals) ----------------------------------
__device__ __align__(16) __half g_h16[BN_ * HF_];
__device__ __align__(16) float  g_ssrc[BN_ * H_];
__device__ __align__(16) float  g_sdst[BN_ * H_];
__device__ int g_nbrs[N_ * MAXD];
__device__ int g_deg[N_];

// ---------------------------------------------------------------------------
__device__ __forceinline__ uint32_t tf32_rna(float a) {
    uint32_t u;
    asm("cvt.rna.tf32.f32 %0, %1;" : "=r"(u) : "f"(a));
    return u;
}

__device__ __forceinline__ void mma_tf32(float c[4],
                                         uint32_t a0, uint32_t a1, uint32_t a2, uint32_t a3,
                                         uint32_t b0, uint32_t b1)
{
    asm volatile(
        "mma.sync.aligned.m16n8k8.row.col.f32.tf32.tf32.f32 "
        "{%0,%1,%2,%3},{%4,%5,%6,%7},{%8,%9},{%0,%1,%2,%3};"
        : "+f"(c[0]), "+f"(c[1]), "+f"(c[2]), "+f"(c[3])
        : "r"(a0), "r"(a1), "r"(a2), "r"(a3), "r"(b0), "r"(b1));
}

__device__ __forceinline__ void cp16(uint32_t dst_smem, const void* src) {
    asm volatile("cp.async.cg.shared.global [%0], [%1], 16;" :: "r"(dst_smem), "l"(src));
}
__device__ __forceinline__ void cp_commit() {
    asm volatile("cp.async.commit_group;");
}
__device__ __forceinline__ void cp_wait_all() {
    asm volatile("cp.async.wait_group 0;");
}

// warp-aggregated neighbor emit: one atomic per warp per nonempty ballot
__device__ __forceinline__ void emit_nbr(int r, int n, float val, int idx,
                                         int* cnt, int lane)
{
    const unsigned mask = __ballot_sync(0xFFFFFFFFu, val != 0.0f);
    if (mask == 0) return;                       // uniform across warp
    const int total  = __popc(mask);
    const int leader = __ffs(mask) - 1;
    int base = 0;
    if (lane == leader) base = atomicAdd(&cnt[r], total);
    base = __shfl_sync(0xFFFFFFFFu, base, leader);
    if (val != 0.0f) {
        const int p = base + __popc(mask & ((1u << lane) - 1));
        if (p < MAXD) g_nbrs[n * MAXD + p] = idx;
    }
}

// ---------------------------------------------------------------------------
// Kernel 1 (fused): blocks [0,256) = TF32 GEMM (cp.async double-buffered,
// rna at fragment load); blocks [256,256+2048) = adjacency scan, 2 rows per
// block, MLP-8 loads + warp-aggregated atomics.
// ---------------------------------------------------------------------------
#define GBM 128
#define GBN 64
#define GBK 32
#define GPAD 36
#define KITERS (INF_ / GBK)   // 8

__global__ __launch_bounds__(256, 4) void fused_gemm_csr(const float* __restrict__ x,
                                                         const float* __restrict__ W,
                                                         const float* __restrict__ a_src,
                                                         const float* __restrict__ a_dst,
                                                         const float* __restrict__ adj)
{
    __shared__ __align__(16) float As[2][GBM][GPAD];
    __shared__ __align__(16) float Bs[2][GBN][GPAD];
    __shared__ float sS[GBM], sD[GBM];
    __shared__ int cnt[2];

    const int bid = blockIdx.x;
    const int t   = threadIdx.x;

    // ================= CSR path: 2 rows per block =================
    if (bid >= GEMM_BLOCKS) {
        const int n0 = (bid - GEMM_BLOCKS) * 2;
        if (t < 2) cnt[t] = 0;
        __syncthreads();

        const int r    = t >> 7;
        const int tt   = t & 127;
        const int lane = t & 31;
        const int n    = n0 + r;
        const float4* row4 = reinterpret_cast<const float4*>(adj + (long long)n * N_);

        float4 v[8];
#pragma unroll
        for (int j = 0; j < 8; j++)
            v[j] = row4[tt + 128 * j];

#pragma unroll
        for (int j = 0; j < 8; j++) {
            const int base = (tt + 128 * j) * 4;
            emit_nbr(r, n, v[j].x, base + 0, cnt, lane);
            emit_nbr(r, n, v[j].y, base + 1, cnt, lane);
            emit_nbr(r, n, v[j].z, base + 2, cnt, lane);
            emit_nbr(r, n, v[j].w, base + 3, cnt, lane);
        }
        __syncthreads();
        if (t < 2) g_deg[n0 + t] = cnt[t] < MAXD ? cnt[t] : MAXD;
        return;
    }

    // ================= GEMM path =================
    const int head = bid & 3;
    const int bm   = (bid >> 2) * GBM;
    const int bo   = head * GBN;

    const int lane = t & 31;
    const int warp = t >> 5;
    const int wm   = warp >> 2;
    const int wn   = warp & 3;

    if (t < GBM) { sS[t] = 0.0f; sD[t] = 0.0f; }

    float acc[4][2][4];
#pragma unroll
    for (int mt = 0; mt < 4; mt++)
#pragma unroll
        for (int nt = 0; nt < 2; nt++)
#pragma unroll
            for (int i = 0; i < 4; i++) acc[mt][nt][i] = 0.0f;

    const int arow = t >> 3;
    const int acol = (t & 7) * 4;

    uint32_t asA[2][4], asB[2][2];
#pragma unroll
    for (int bufi = 0; bufi < 2; bufi++) {
#pragma unroll
        for (int j = 0; j < 4; j++)
            asA[bufi][j] = (uint32_t)__cvta_generic_to_shared(&As[bufi][arow + 32 * j][acol]);
#pragma unroll
        for (int j = 0; j < 2; j++)
            asB[bufi][j] = (uint32_t)__cvta_generic_to_shared(&Bs[bufi][arow + 32 * j][acol]);
    }

#pragma unroll
    for (int j = 0; j < 4; j++)
        cp16(asA[0][j], &x[(bm + arow + 32 * j) * INF_ + acol]);
#pragma unroll
    for (int j = 0; j < 2; j++)
        cp16(asB[0][j], &W[(bo + arow + 32 * j) * INF_ + acol]);
    cp_commit();

#pragma unroll
    for (int kt = 0; kt < KITERS; kt++) {
        const int cur = kt & 1;
        const int nxt = cur ^ 1;

        cp_wait_all();
        __syncthreads();

        if (kt + 1 < KITERS) {
            const int k0 = (kt + 1) * GBK;
#pragma unroll
            for (int j = 0; j < 4; j++)
                cp16(asA[nxt][j], &x[(bm + arow + 32 * j) * INF_ + k0 + acol]);
#pragma unroll
            for (int j = 0; j < 2; j++)
                cp16(asB[nxt][j], &W[(bo + arow + 32 * j) * INF_ + k0 + acol]);
            cp_commit();
        }

#pragma unroll
        for (int ks = 0; ks < 4; ks++) {
            const int kc = ks * 8 + (lane & 3);
            uint32_t Af[4][4];
#pragma unroll
            for (int mt = 0; mt < 4; mt++) {
                const int r0 = wm * 64 + mt * 16 + (lane >> 2);
                Af[mt][0] = tf32_rna(As[cur][r0][kc]);
                Af[mt][1] = tf32_rna(As[cur][r0 + 8][kc]);
                Af[mt][2] = tf32_rna(As[cur][r0][kc + 4]);
                Af[mt][3] = tf32_rna(As[cur][r0 + 8][kc + 4]);
            }
            uint32_t Bf[2][2];
#pragma unroll
            for (int nt = 0; nt < 2; nt++) {
                const int n0 = wn * 16 + nt * 8 + (lane >> 2);
                Bf[nt][0] = tf32_rna(Bs[cur][n0][kc]);
                Bf[nt][1] = tf32_rna(Bs[cur][n0][kc + 4]);
            }
#pragma unroll
            for (int mt = 0; mt < 4; mt++)
#pragma unroll
                for (int nt = 0; nt < 2; nt++)
                    mma_tf32(acc[mt][nt], Af[mt][0], Af[mt][1], Af[mt][2], Af[mt][3],
                             Bf[nt][0], Bf[nt][1]);
        }
    }

#pragma unroll
    for (int mt = 0; mt < 4; mt++) {
#pragma unroll
        for (int nt = 0; nt < 2; nt++) {
            const int row = bm + wm * 64 + mt * 16 + (lane >> 2);
            const int col = bo + wn * 16 + nt * 8 + (lane & 3) * 2;
            float2 v0 = make_float2(acc[mt][nt][0], acc[mt][nt][1]);
            float2 v1 = make_float2(acc[mt][nt][2], acc[mt][nt][3]);
            *reinterpret_cast<__half2*>(&g_h16[row * HF_ + col]) = __float22half2_rn(v0);
            *reinterpret_cast<__half2*>(&g_h16[(row + 8) * HF_ + col]) = __float22half2_rn(v1);
        }
    }

    float asv[2][2], adv[2][2];
#pragma unroll
    for (int nt = 0; nt < 2; nt++)
#pragma unroll
        for (int j = 0; j < 2; j++) {
            const int c = wn * 16 + nt * 8 + (lane & 3) * 2 + j;
            asv[nt][j] = a_src[head * F_ + c];
            adv[nt][j] = a_dst[head * F_ + c];
        }

    __syncthreads();
#pragma unroll
    for (int mt = 0; mt < 4; mt++) {
        float ps0 = 0.f, ps1 = 0.f, pd0 = 0.f, pd1 = 0.f;
#pragma unroll
        for (int nt = 0; nt < 2; nt++) {
            ps0 = fmaf(acc[mt][nt][0], asv[nt][0], ps0);
            ps0 = fmaf(acc[mt][nt][1], asv[nt][1], ps0);
            ps1 = fmaf(acc[mt][nt][2], asv[nt][0], ps1);
            ps1 = fmaf(acc[mt][nt][3], asv[nt][1], ps1);
            pd0 = fmaf(acc[mt][nt][0], adv[nt][0], pd0);
            pd0 = fmaf(acc[mt][nt][1], adv[nt][1], pd0);
            pd1 = fmaf(acc[mt][nt][2], adv[nt][0], pd1);
            pd1 = fmaf(acc[mt][nt][3], adv[nt][1], pd1);
        }
#pragma unroll
        for (int o = 1; o < 4; o <<= 1) {
            ps0 += __shfl_xor_sync(0xFFFFFFFFu, ps0, o);
            ps1 += __shfl_xor_sync(0xFFFFFFFFu, ps1, o);
            pd0 += __shfl_xor_sync(0xFFFFFFFFu, pd0, o);
            pd1 += __shfl_xor_sync(0xFFFFFFFFu, pd1, o);
        }
        if ((lane & 3) == 0) {
            const int r = wm * 64 + mt * 16 + (lane >> 2);
            atomicAdd(&sS[r], ps0);
            atomicAdd(&sS[r + 8], ps1);
            atomicAdd(&sD[r], pd0);
            atomicAdd(&sD[r + 8], pd1);
        }
    }
    __syncthreads();
    if (t < GBM) {
        g_ssrc[(bm + t) * H_ + head] = sS[t];
        g_sdst[(bm + t) * H_ + head] = sD[t];
    }
}

// ---------------------------------------------------------------------------
__device__ __forceinline__ void accum_row(float2& a0, float2& a1, float2& a2, float2& a3,
                                          float p, const uint4& v)
{
    float2 f;
    f = __half22float2(*reinterpret_cast<const __half2*>(&v.x));
    a0.x = fmaf(p, f.x, a0.x); a0.y = fmaf(p, f.y, a0.y);
    f = __half22float2(*reinterpret_cast<const __half2*>(&v.y));
    a1.x = fmaf(p, f.x, a1.x); a1.y = fmaf(p, f.y, a1.y);
    f = __half22float2(*reinterpret_cast<const __half2*>(&v.z));
    a2.x = fmaf(p, f.x, a2.x); a2.y = fmaf(p, f.y, a2.y);
    f = __half22float2(*reinterpret_cast<const __half2*>(&v.w));
    a3.x = fmaf(p, f.x, a3.x); a3.y = fmaf(p, f.y, a3.y);
}

// ---------------------------------------------------------------------------
// Kernel 2 (attn, R9 loop; launch_bounds(128,12) to push occupancy to 12
// blocks/SM = 48 warps).
// ---------------------------------------------------------------------------
#define ATT_NPB 2   // n's per block; 4 warps = {b0,b1} x {n0,n1}

__global__ __launch_bounds__(128, 12) void attn_kernel(float* __restrict__ out)
{
    __shared__ __align__(16) int   nbS[ATT_NPB][MAXD_S];
    __shared__ __align__(16) float pS[4][H_ * PSTR];
    __shared__ int degS[ATT_NPB];

    const int t    = threadIdx.x;
    const int w    = t >> 5;
    const int lane = t & 31;
    const int b    = w & 1;
    const int nsub = w >> 1;
    const int n    = blockIdx.x * ATT_NPB + nsub;
    const int bn   = b * N_ + n;

    if (b == 0) {
        if (lane == 0) degS[nsub] = g_deg[n];
        const int dg = g_deg[n];
        for (int i = lane; i < dg && i < MAXD_S; i += 32)
            nbS[nsub][i] = g_nbrs[n * MAXD + i];
    }
    __syncthreads();

    const int deg  = degS[nsub];
    const int degc = deg < MAXD_S ? deg : MAXD_S;
    const int bN   = b * N_;

    const float4 c4 = *reinterpret_cast<const float4*>(&g_ssrc[bn * H_]);
    const float4* __restrict__ sd4 = reinterpret_cast<const float4*>(g_sdst);

    // ---- phase 1: strided p computation (all heads), padded head-major smem
    float4 sum4 = make_float4(0.f, 0.f, 0.f, 0.f);
    for (int i = lane; i < degc; i += 32) {
        const int m = nbS[nsub][i];
        float4 sdv = sd4[bN + m];
        float ex = c4.x + sdv.x, ey = c4.y + sdv.y, ez = c4.z + sdv.z, ew = c4.w + sdv.w;
        ex = fmaxf(ex, 0.2f * ex);
        ey = fmaxf(ey, 0.2f * ey);
        ez = fmaxf(ez, 0.2f * ez);
        ew = fmaxf(ew, 0.2f * ew);
        float px = __expf(ex), py = __expf(ey), pz = __expf(ez), pw = __expf(ew);
        pS[w][0 * PSTR + i] = px;
        pS[w][1 * PSTR + i] = py;
        pS[w][2 * PSTR + i] = pz;
        pS[w][3 * PSTR + i] = pw;
        sum4.x += px; sum4.y += py; sum4.z += pz; sum4.w += pw;
    }
    for (int i = degc + lane; i < deg; i += 32) {
        const int m = g_nbrs[n * MAXD + i];
        float4 sdv = sd4[bN + m];
        float ex = c4.x + sdv.x, ey = c4.y + sdv.y, ez = c4.z + sdv.z, ew = c4.w + sdv.w;
        ex = fmaxf(ex, 0.2f * ex);
        ey = fmaxf(ey, 0.2f * ey);
        ez = fmaxf(ez, 0.2f * ez);
        ew = fmaxf(ew, 0.2f * ew);
        sum4.x += __expf(ex); sum4.y += __expf(ey); sum4.z += __expf(ez); sum4.w += __expf(ew);
    }
#pragma unroll
    for (int o = 16; o > 0; o >>= 1) {
        sum4.x += __shfl_xor_sync(0xFFFFFFFFu, sum4.x, o);
        sum4.y += __shfl_xor_sync(0xFFFFFFFFu, sum4.y, o);
        sum4.z += __shfl_xor_sync(0xFFFFFFFFu, sum4.z, o);
        sum4.w += __shfl_xor_sync(0xFFFFFFFFu, sum4.w, o);
    }

    const int head = lane >> 3;
    float invh = (head & 2) ? ((head & 1) ? sum4.w : sum4.z)
                            : ((head & 1) ? sum4.y : sum4.x);
    invh = 1.0f / invh;

    __syncwarp();

    // ---- phase 2: gather + weighted accumulate, unrolled x4 (MLP 4)
    const uint4* __restrict__ hrow = reinterpret_cast<const uint4*>(g_h16) + (long long)bN * 32 + lane;
    const float* __restrict__ pw = &pS[w][head * PSTR];
    const int*   __restrict__ nbp = &nbS[nsub][0];

    float2 a0 = make_float2(0.f, 0.f), a1 = a0, a2 = a0, a3 = a0;

    int i = 0;
    for (; i + 4 <= degc; i += 4) {
        const int4   mm = *reinterpret_cast<const int4*>(&nbp[i]);
        const float4 pp = *reinterpret_cast<const float4*>(&pw[i]);
        const uint4 v0 = hrow[mm.x * 32];
        const uint4 v1 = hrow[mm.y * 32];
        const uint4 v2 = hrow[mm.z * 32];
        const uint4 v3 = hrow[mm.w * 32];
        accum_row(a0, a1, a2, a3, pp.x, v0);
        accum_row(a0, a1, a2, a3, pp.y, v1);
        accum_row(a0, a1, a2, a3, pp.z, v2);
        accum_row(a0, a1, a2, a3, pp.w, v3);
    }
    for (; i < degc; i++) {
        const float p0 = pw[i];
        const uint4 v0 = hrow[nbp[i] * 32];
        accum_row(a0, a1, a2, a3, p0, v0);
    }
    // tail beyond smem capacity: recompute p on the fly (statistically never)
    for (i = degc; i < deg; i++) {
        const int m0 = g_nbrs[n * MAXD + i];
        float4 sdv = sd4[bN + m0];
        float e = ((head & 2) ? ((head & 1) ? c4.w + sdv.w : c4.z + sdv.z)
                              : ((head & 1) ? c4.y + sdv.y : c4.x + sdv.x));
        e = fmaxf(e, 0.2f * e);
        const float p0 = __expf(e);
        const uint4 v0 = hrow[m0 * 32];
        accum_row(a0, a1, a2, a3, p0, v0);
    }

    float4 o0 = make_float4(a0.x * invh, a0.y * invh, a1.x * invh, a1.y * invh);
    float4 o1 = make_float4(a2.x * invh, a2.y * invh, a3.x * invh, a3.y * invh);
    float4* outp = reinterpret_cast<float4*>(out);
    outp[bn * 64 + lane * 2 + 0] = o0;
    outp[bn * 64 + lane * 2 + 1] = o1;
}

// ---------------------------------------------------------------------------
extern "C" void kernel_launch(void* const* d_in, const int* in_sizes, int n_in,
                              void* d_out, int out_size)
{
    const float* x     = (const float*)d_in[0];
    const float* adj   = (const float*)d_in[1];
    const float* W     = (const float*)d_in[2];
    const float* a_src = (const float*)d_in[3];
    const float* a_dst = (const float*)d_in[4];
    float* out = (float*)d_out;

    fused_gemm_csr<<<GEMM_BLOCKS + CSR_BLOCKS, 256>>>(x, W, a_src, a_dst, adj);
    attn_kernel<<<N_ / ATT_NPB, 128>>>(out);
}

// round 14
// speedup vs baseline: 1.0039x; 1.0039x over previous
#include <cuda_runtime.h>
#include <cuda_bf16.h>
#include <cuda_fp16.h>
#include <cstdint>

#define B_   2
#define N_   4096
#define INF_ 256
#define H_   4
#define F_   64
#define BN_  (B_ * N_)      // 8192
#define HF_  (H_ * F_)      // 256
#define MAXD   512
#define MAXD_S 128          // smem capacity (deg mean ~82, P(>128)~1e-7; tail fallback correct)
#define PSTR   (MAXD_S + 4) // 132: bank-shift -> conflict-free float4 LDS

#define GEMM_BLOCKS 256     // (BN_/GBM) * (HF_/GBN) = 64*4
#define CSR_BLOCKS  (N_ / 2)  // 2 adjacency rows per block
#define TOTAL_BLOCKS (GEMM_BLOCKS + CSR_BLOCKS)   // 2304 = 256 * 9

// ---------------- scratch (device globals) ----------------------------------
__device__ __align__(16) __half g_h16[BN_ * HF_];
__device__ __align__(16) float  g_ssrc[BN_ * H_];
__device__ __align__(16) float  g_sdst[BN_ * H_];
__device__ int g_nbrs[N_ * MAXD];
__device__ int g_deg[N_];

// ---------------------------------------------------------------------------
__device__ __forceinline__ uint32_t tf32_rna(float a) {
    uint32_t u;
    asm("cvt.rna.tf32.f32 %0, %1;" : "=r"(u) : "f"(a));
    return u;
}

__device__ __forceinline__ void mma_tf32(float c[4],
                                         uint32_t a0, uint32_t a1, uint32_t a2, uint32_t a3,
                                         uint32_t b0, uint32_t b1)
{
    asm volatile(
        "mma.sync.aligned.m16n8k8.row.col.f32.tf32.tf32.f32 "
        "{%0,%1,%2,%3},{%4,%5,%6,%7},{%8,%9},{%0,%1,%2,%3};"
        : "+f"(c[0]), "+f"(c[1]), "+f"(c[2]), "+f"(c[3])
        : "r"(a0), "r"(a1), "r"(a2), "r"(a3), "r"(b0), "r"(b1));
}

__device__ __forceinline__ void cp16(uint32_t dst_smem, const void* src) {
    asm volatile("cp.async.cg.shared.global [%0], [%1], 16;" :: "r"(dst_smem), "l"(src));
}
__device__ __forceinline__ void cp_commit() {
    asm volatile("cp.async.commit_group;");
}
__device__ __forceinline__ void cp_wait_all() {
    asm volatile("cp.async.wait_group 0;");
}

// ---------------------------------------------------------------------------
// Kernel 1 (fused): gemm/csr block INTERLEAVE — bid % 9 == 8 -> GEMM block
// (index bid/9), else CSR block (index bid - bid/9 - (bid%9==8?1:0)).
// Every scheduling wave co-runs DRAM-bound csr with tensor-bound gemm.
// GEMM: TF32 cp.async double-buffered, rna at fragment load (R12 form).
// CSR: 2 rows per block, MLP-8 front-batched loads, plain smem atomics (R12).
// ---------------------------------------------------------------------------
#define GBM 128
#define GBN 64
#define GBK 32
#define GPAD 36
#define KITERS (INF_ / GBK)   // 8

__global__ __launch_bounds__(256, 4) void fused_gemm_csr(const float* __restrict__ x,
                                                         const float* __restrict__ W,
                                                         const float* __restrict__ a_src,
                                                         const float* __restrict__ a_dst,
                                                         const float* __restrict__ adj)
{
    __shared__ __align__(16) float As[2][GBM][GPAD];
    __shared__ __align__(16) float Bs[2][GBN][GPAD];
    __shared__ float sS[GBM], sD[GBM];
    __shared__ int cnt[2];

    const int bid  = blockIdx.x;
    const int t    = threadIdx.x;
    const int gsel = (bid % 9) == 8;       // 1 -> gemm, 0 -> csr
    const int gidx = bid / 9;              // gemm block index when gsel

    // ================= CSR path: 2 rows per block =================
    if (!gsel) {
        const int cidx = bid - gidx;       // csr block index (0..2047)
        const int n0 = cidx * 2;
        if (t < 2) cnt[t] = 0;
        __syncthreads();

        const int r  = t >> 7;
        const int tt = t & 127;
        const int n  = n0 + r;
        const float4* row4 = reinterpret_cast<const float4*>(adj + (long long)n * N_);

        float4 v[8];
#pragma unroll
        for (int j = 0; j < 8; j++)
            v[j] = row4[tt + 128 * j];

#pragma unroll
        for (int j = 0; j < 8; j++) {
            const int base = (tt + 128 * j) * 4;
            if (v[j].x != 0.0f) { int p = atomicAdd(&cnt[r], 1); if (p < MAXD) g_nbrs[n * MAXD + p] = base + 0; }
            if (v[j].y != 0.0f) { int p = atomicAdd(&cnt[r], 1); if (p < MAXD) g_nbrs[n * MAXD + p] = base + 1; }
            if (v[j].z != 0.0f) { int p = atomicAdd(&cnt[r], 1); if (p < MAXD) g_nbrs[n * MAXD + p] = base + 2; }
            if (v[j].w != 0.0f) { int p = atomicAdd(&cnt[r], 1); if (p < MAXD) g_nbrs[n * MAXD + p] = base + 3; }
        }
        __syncthreads();
        if (t < 2) g_deg[n0 + t] = cnt[t] < MAXD ? cnt[t] : MAXD;
        return;
    }

    // ================= GEMM path =================
    const int head = gidx & 3;
    const int bm   = (gidx >> 2) * GBM;
    const int bo   = head * GBN;

    const int lane = t & 31;
    const int warp = t >> 5;
    const int wm   = warp >> 2;
    const int wn   = warp & 3;

    if (t < GBM) { sS[t] = 0.0f; sD[t] = 0.0f; }

    float acc[4][2][4];
#pragma unroll
    for (int mt = 0; mt < 4; mt++)
#pragma unroll
        for (int nt = 0; nt < 2; nt++)
#pragma unroll
            for (int i = 0; i < 4; i++) acc[mt][nt][i] = 0.0f;

    const int arow = t >> 3;
    const int acol = (t & 7) * 4;

    uint32_t asA[2][4], asB[2][2];
#pragma unroll
    for (int bufi = 0; bufi < 2; bufi++) {
#pragma unroll
        for (int j = 0; j < 4; j++)
            asA[bufi][j] = (uint32_t)__cvta_generic_to_shared(&As[bufi][arow + 32 * j][acol]);
#pragma unroll
        for (int j = 0; j < 2; j++)
            asB[bufi][j] = (uint32_t)__cvta_generic_to_shared(&Bs[bufi][arow + 32 * j][acol]);
    }

#pragma unroll
    for (int j = 0; j < 4; j++)
        cp16(asA[0][j], &x[(bm + arow + 32 * j) * INF_ + acol]);
#pragma unroll
    for (int j = 0; j < 2; j++)
        cp16(asB[0][j], &W[(bo + arow + 32 * j) * INF_ + acol]);
    cp_commit();

#pragma unroll
    for (int kt = 0; kt < KITERS; kt++) {
        const int cur = kt & 1;
        const int nxt = cur ^ 1;

        cp_wait_all();
        __syncthreads();

        if (kt + 1 < KITERS) {
            const int k0 = (kt + 1) * GBK;
#pragma unroll
            for (int j = 0; j < 4; j++)
                cp16(asA[nxt][j], &x[(bm + arow + 32 * j) * INF_ + k0 + acol]);
#pragma unroll
            for (int j = 0; j < 2; j++)
                cp16(asB[nxt][j], &W[(bo + arow + 32 * j) * INF_ + k0 + acol]);
            cp_commit();
        }

#pragma unroll
        for (int ks = 0; ks < 4; ks++) {
            const int kc = ks * 8 + (lane & 3);
            uint32_t Af[4][4];
#pragma unroll
            for (int mt = 0; mt < 4; mt++) {
                const int r0 = wm * 64 + mt * 16 + (lane >> 2);
                Af[mt][0] = tf32_rna(As[cur][r0][kc]);
                Af[mt][1] = tf32_rna(As[cur][r0 + 8][kc]);
                Af[mt][2] = tf32_rna(As[cur][r0][kc + 4]);
                Af[mt][3] = tf32_rna(As[cur][r0 + 8][kc + 4]);
            }
            uint32_t Bf[2][2];
#pragma unroll
            for (int nt = 0; nt < 2; nt++) {
                const int n0 = wn * 16 + nt * 8 + (lane >> 2);
                Bf[nt][0] = tf32_rna(Bs[cur][n0][kc]);
                Bf[nt][1] = tf32_rna(Bs[cur][n0][kc + 4]);
            }
#pragma unroll
            for (int mt = 0; mt < 4; mt++)
#pragma unroll
                for (int nt = 0; nt < 2; nt++)
                    mma_tf32(acc[mt][nt], Af[mt][0], Af[mt][1], Af[mt][2], Af[mt][3],
                             Bf[nt][0], Bf[nt][1]);
        }
    }

#pragma unroll
    for (int mt = 0; mt < 4; mt++) {
#pragma unroll
        for (int nt = 0; nt < 2; nt++) {
            const int row = bm + wm * 64 + mt * 16 + (lane >> 2);
            const int col = bo + wn * 16 + nt * 8 + (lane & 3) * 2;
            float2 v0 = make_float2(acc[mt][nt][0], acc[mt][nt][1]);
            float2 v1 = make_float2(acc[mt][nt][2], acc[mt][nt][3]);
            *reinterpret_cast<__half2*>(&g_h16[row * HF_ + col]) = __float22half2_rn(v0);
            *reinterpret_cast<__half2*>(&g_h16[(row + 8) * HF_ + col]) = __float22half2_rn(v1);
        }
    }

    float asv[2][2], adv[2][2];
#pragma unroll
    for (int nt = 0; nt < 2; nt++)
#pragma unroll
        for (int j = 0; j < 2; j++) {
            const int c = wn * 16 + nt * 8 + (lane & 3) * 2 + j;
            asv[nt][j] = a_src[head * F_ + c];
            adv[nt][j] = a_dst[head * F_ + c];
        }

    __syncthreads();
#pragma unroll
    for (int mt = 0; mt < 4; mt++) {
        float ps0 = 0.f, ps1 = 0.f, pd0 = 0.f, pd1 = 0.f;
#pragma unroll
        for (int nt = 0; nt < 2; nt++) {
            ps0 = fmaf(acc[mt][nt][0], asv[nt][0], ps0);
            ps0 = fmaf(acc[mt][nt][1], asv[nt][1], ps0);
            ps1 = fmaf(acc[mt][nt][2], asv[nt][0], ps1);
            ps1 = fmaf(acc[mt][nt][3], asv[nt][1], ps1);
            pd0 = fmaf(acc[mt][nt][0], adv[nt][0], pd0);
            pd0 = fmaf(acc[mt][nt][1], adv[nt][1], pd0);
            pd1 = fmaf(acc[mt][nt][2], adv[nt][0], pd1);
            pd1 = fmaf(acc[mt][nt][3], adv[nt][1], pd1);
        }
#pragma unroll
        for (int o = 1; o < 4; o <<= 1) {
            ps0 += __shfl_xor_sync(0xFFFFFFFFu, ps0, o);
            ps1 += __shfl_xor_sync(0xFFFFFFFFu, ps1, o);
            pd0 += __shfl_xor_sync(0xFFFFFFFFu, pd0, o);
            pd1 += __shfl_xor_sync(0xFFFFFFFFu, pd1, o);
        }
        if ((lane & 3) == 0) {
            const int r = wm * 64 + mt * 16 + (lane >> 2);
            atomicAdd(&sS[r], ps0);
            atomicAdd(&sS[r + 8], ps1);
            atomicAdd(&sD[r], pd0);
            atomicAdd(&sD[r + 8], pd1);
        }
    }
    __syncthreads();
    if (t < GBM) {
        g_ssrc[(bm + t) * H_ + head] = sS[t];
        g_sdst[(bm + t) * H_ + head] = sD[t];
    }
}

// ---------------------------------------------------------------------------
__device__ __forceinline__ void accum_row(float2& a0, float2& a1, float2& a2, float2& a3,
                                          float p, const uint4& v)
{
    float2 f;
    f = __half22float2(*reinterpret_cast<const __half2*>(&v.x));
    a0.x = fmaf(p, f.x, a0.x); a0.y = fmaf(p, f.y, a0.y);
    f = __half22float2(*reinterpret_cast<const __half2*>(&v.y));
    a1.x = fmaf(p, f.x, a1.x); a1.y = fmaf(p, f.y, a1.y);
    f = __half22float2(*reinterpret_cast<const __half2*>(&v.z));
    a2.x = fmaf(p, f.x, a2.x); a2.y = fmaf(p, f.y, a2.y);
    f = __half22float2(*reinterpret_cast<const __half2*>(&v.w));
    a3.x = fmaf(p, f.x, a3.x); a3.y = fmaf(p, f.y, a3.y);
}

// ---------------------------------------------------------------------------
// Kernel 2 (attn, exact R12/R9 form — measured best 32.8us; L2-BW-bound).
// ---------------------------------------------------------------------------
#define ATT_NPB 2   // n's per block; 4 warps = {b0,b1} x {n0,n1}

__global__ __launch_bounds__(128, 10) void attn_kernel(float* __restrict__ out)
{
    __shared__ __align__(16) int   nbS[ATT_NPB][MAXD_S];
    __shared__ __align__(16) float pS[4][H_ * PSTR];
    __shared__ int degS[ATT_NPB];

    const int t    = threadIdx.x;
    const int w    = t >> 5;
    const int lane = t & 31;
    const int b    = w & 1;
    const int nsub = w >> 1;
    const int n    = blockIdx.x * ATT_NPB + nsub;
    const int bn   = b * N_ + n;

    if (b == 0) {
        if (lane == 0) degS[nsub] = g_deg[n];
        const int dg = g_deg[n];
        for (int i = lane; i < dg && i < MAXD_S; i += 32)
            nbS[nsub][i] = g_nbrs[n * MAXD + i];
    }
    __syncthreads();

    const int deg  = degS[nsub];
    const int degc = deg < MAXD_S ? deg : MAXD_S;
    const int bN   = b * N_;

    const float4 c4 = *reinterpret_cast<const float4*>(&g_ssrc[bn * H_]);
    const float4* __restrict__ sd4 = reinterpret_cast<const float4*>(g_sdst);

    // ---- phase 1: strided p computation (all heads), padded head-major smem
    float4 sum4 = make_float4(0.f, 0.f, 0.f, 0.f);
    for (int i = lane; i < degc; i += 32) {
        const int m = nbS[nsub][i];
        float4 sdv = sd4[bN + m];
        float ex = c4.x + sdv.x, ey = c4.y + sdv.y, ez = c4.z + sdv.z, ew = c4.w + sdv.w;
        ex = fmaxf(ex, 0.2f * ex);
        ey = fmaxf(ey, 0.2f * ey);
        ez = fmaxf(ez, 0.2f * ez);
        ew = fmaxf(ew, 0.2f * ew);
        float px = __expf(ex), py = __expf(ey), pz = __expf(ez), pw = __expf(ew);
        pS[w][0 * PSTR + i] = px;
        pS[w][1 * PSTR + i] = py;
        pS[w][2 * PSTR + i] = pz;
        pS[w][3 * PSTR + i] = pw;
        sum4.x += px; sum4.y += py; sum4.z += pz; sum4.w += pw;
    }
    for (int i = degc + lane; i < deg; i += 32) {
        const int m = g_nbrs[n * MAXD + i];
        float4 sdv = sd4[bN + m];
        float ex = c4.x + sdv.x, ey = c4.y + sdv.y, ez = c4.z + sdv.z, ew = c4.w + sdv.w;
        ex = fmaxf(ex, 0.2f * ex);
        ey = fmaxf(ey, 0.2f * ey);
        ez = fmaxf(ez, 0.2f * ez);
        ew = fmaxf(ew, 0.2f * ew);
        sum4.x += __expf(ex); sum4.y += __expf(ey); sum4.z += __expf(ez); sum4.w += __expf(ew);
    }
#pragma unroll
    for (int o = 16; o > 0; o >>= 1) {
        sum4.x += __shfl_xor_sync(0xFFFFFFFFu, sum4.x, o);
        sum4.y += __shfl_xor_sync(0xFFFFFFFFu, sum4.y, o);
        sum4.z += __shfl_xor_sync(0xFFFFFFFFu, sum4.z, o);
        sum4.w += __shfl_xor_sync(0xFFFFFFFFu, sum4.w, o);
    }

    const int head = lane >> 3;
    float invh = (head & 2) ? ((head & 1) ? sum4.w : sum4.z)
                            : ((head & 1) ? sum4.y : sum4.x);
    invh = 1.0f / invh;

    __syncwarp();

    // ---- phase 2: gather + weighted accumulate, unrolled x4 (MLP 4)
    const uint4* __restrict__ hrow = reinterpret_cast<const uint4*>(g_h16) + (long long)bN * 32 + lane;
    const float* __restrict__ pw = &pS[w][head * PSTR];
    const int*   __restrict__ nbp = &nbS[nsub][0];

    float2 a0 = make_float2(0.f, 0.f), a1 = a0, a2 = a0, a3 = a0;

    int i = 0;
    for (; i + 4 <= degc; i += 4) {
        const int4   mm = *reinterpret_cast<const int4*>(&nbp[i]);
        const float4 pp = *reinterpret_cast<const float4*>(&pw[i]);
        const uint4 v0 = hrow[mm.x * 32];
        const uint4 v1 = hrow[mm.y * 32];
        const uint4 v2 = hrow[mm.z * 32];
        const uint4 v3 = hrow[mm.w * 32];
        accum_row(a0, a1, a2, a3, pp.x, v0);
        accum_row(a0, a1, a2, a3, pp.y, v1);
        accum_row(a0, a1, a2, a3, pp.z, v2);
        accum_row(a0, a1, a2, a3, pp.w, v3);
    }
    for (; i < degc; i++) {
        const float p0 = pw[i];
        const uint4 v0 = hrow[nbp[i] * 32];
        accum_row(a0, a1, a2, a3, p0, v0);
    }
    // tail beyond smem capacity: recompute p on the fly (statistically never)
    for (i = degc; i < deg; i++) {
        const int m0 = g_nbrs[n * MAXD + i];
        float4 sdv = sd4[bN + m0];
        float e = ((head & 2) ? ((head & 1) ? c4.w + sdv.w : c4.z + sdv.z)
                              : ((head & 1) ? c4.y + sdv.y : c4.x + sdv.x));
        e = fmaxf(e, 0.2f * e);
        const float p0 = __expf(e);
        const uint4 v0 = hrow[m0 * 32];
        accum_row(a0, a1, a2, a3, p0, v0);
    }

    float4 o0 = make_float4(a0.x * invh, a0.y * invh, a1.x * invh, a1.y * invh);
    float4 o1 = make_float4(a2.x * invh, a2.y * invh, a3.x * invh, a3.y * invh);
    float4* outp = reinterpret_cast<float4*>(out);
    outp[bn * 64 + lane * 2 + 0] = o0;
    outp[bn * 64 + lane * 2 + 1] = o1;
}

// ---------------------------------------------------------------------------
extern "C" void kernel_launch(void* const* d_in, const int* in_sizes, int n_in,
                              void* d_out, int out_size)
{
    const float* x     = (const float*)d_in[0];
    const float* adj   = (const float*)d_in[1];
    const float* W     = (const float*)d_in[2];
    const float* a_src = (const float*)d_in[3];
    const float* a_dst = (const float*)d_in[4];
    float* out = (float*)d_out;

    fused_gemm_csr<<<TOTAL_BLOCKS, 256>>>(x, W, a_src, a_dst, adj);
    attn_kernel<<<N_ / ATT_NPB, 128>>>(out);
}

// round 15
// speedup vs baseline: 1.2124x; 1.2077x over previous
#include <cuda_runtime.h>
#include <cuda_bf16.h>
#include <cuda_fp16.h>
#include <cstdint>

#define B_   2
#define N_   4096
#define INF_ 256
#define H_   4
#define F_   64
#define BN_  (B_ * N_)      // 8192
#define HF_  (H_ * F_)      // 256
#define MAXD   512
#define MAXD_S 128          // smem capacity (deg mean ~82, P(>128)~1e-7; tail fallback correct)
#define PSTR   (MAXD_S + 4) // 132: bank-shift -> conflict-free float4 LDS

#define GEMM_BLOCKS 512     // (BN_/GBM=64) * (HF_/GBN) = 128*4
#define CSR_BLOCKS  (N_ / 2)  // 2 adjacency rows per block

// ---------------- scratch (device globals) ----------------------------------
__device__ __align__(16) __half g_h16[BN_ * HF_];
__device__ __align__(16) float  g_ssrc[BN_ * H_];
__device__ __align__(16) float  g_sdst[BN_ * H_];
__device__ int g_nbrs[N_ * MAXD];
__device__ int g_deg[N_];

// ---------------------------------------------------------------------------
__device__ __forceinline__ uint32_t tf32_rna(float a) {
    uint32_t u;
    asm("cvt.rna.tf32.f32 %0, %1;" : "=r"(u) : "f"(a));
    return u;
}

__device__ __forceinline__ void mma_tf32(float c[4],
                                         uint32_t a0, uint32_t a1, uint32_t a2, uint32_t a3,
                                         uint32_t b0, uint32_t b1)
{
    asm volatile(
        "mma.sync.aligned.m16n8k8.row.col.f32.tf32.tf32.f32 "
        "{%0,%1,%2,%3},{%4,%5,%6,%7},{%8,%9},{%0,%1,%2,%3};"
        : "+f"(c[0]), "+f"(c[1]), "+f"(c[2]), "+f"(c[3])
        : "r"(a0), "r"(a1), "r"(a2), "r"(a3), "r"(b0), "r"(b1));
}

__device__ __forceinline__ void cp16(uint32_t dst_smem, const void* src) {
    asm volatile("cp.async.cg.shared.global [%0], [%1], 16;" :: "r"(dst_smem), "l"(src));
}
__device__ __forceinline__ void cp_commit() {
    asm volatile("cp.async.commit_group;");
}
__device__ __forceinline__ void cp_wait_all() {
    asm volatile("cp.async.wait_group 0;");
}

// ---------------------------------------------------------------------------
// Kernel 1 (fused): blocks [0,512) = TF32 GEMM with 64x64 tiles (fine-grained
// for cross-SM balance; all gemm blocks land in wave 1); blocks
// [512,512+2048) = adjacency scan (R12 form: MLP-8, plain smem atomics).
// ---------------------------------------------------------------------------
#define GBM 64
#define GBN 64
#define GBK 32
#define GPAD 36
#define KITERS (INF_ / GBK)   // 8

__global__ __launch_bounds__(256, 4) void fused_gemm_csr(const float* __restrict__ x,
                                                         const float* __restrict__ W,
                                                         const float* __restrict__ a_src,
                                                         const float* __restrict__ a_dst,
                                                         const float* __restrict__ adj)
{
    __shared__ __align__(16) float As[2][GBM][GPAD];
    __shared__ __align__(16) float Bs[2][GBN][GPAD];
    __shared__ float sS[GBM], sD[GBM];
    __shared__ int cnt[2];

    const int bid = blockIdx.x;
    const int t   = threadIdx.x;

    // ================= CSR path: 2 rows per block =================
    if (bid >= GEMM_BLOCKS) {
        const int n0 = (bid - GEMM_BLOCKS) * 2;
        if (t < 2) cnt[t] = 0;
        __syncthreads();

        const int r  = t >> 7;
        const int tt = t & 127;
        const int n  = n0 + r;
        const float4* row4 = reinterpret_cast<const float4*>(adj + (long long)n * N_);

        float4 v[8];
#pragma unroll
        for (int j = 0; j < 8; j++)
            v[j] = row4[tt + 128 * j];

#pragma unroll
        for (int j = 0; j < 8; j++) {
            const int base = (tt + 128 * j) * 4;
            if (v[j].x != 0.0f) { int p = atomicAdd(&cnt[r], 1); if (p < MAXD) g_nbrs[n * MAXD + p] = base + 0; }
            if (v[j].y != 0.0f) { int p = atomicAdd(&cnt[r], 1); if (p < MAXD) g_nbrs[n * MAXD + p] = base + 1; }
            if (v[j].z != 0.0f) { int p = atomicAdd(&cnt[r], 1); if (p < MAXD) g_nbrs[n * MAXD + p] = base + 2; }
            if (v[j].w != 0.0f) { int p = atomicAdd(&cnt[r], 1); if (p < MAXD) g_nbrs[n * MAXD + p] = base + 3; }
        }
        __syncthreads();
        if (t < 2) g_deg[n0 + t] = cnt[t] < MAXD ? cnt[t] : MAXD;
        return;
    }

    // ================= GEMM path: 64x64 tile, 8 warps = 2(m) x 4(n) =========
    const int head = bid & 3;
    const int bm   = (bid >> 2) * GBM;
    const int bo   = head * GBN;

    const int lane = t & 31;
    const int warp = t >> 5;
    const int wm   = warp >> 2;   // 0..1 -> 32-row slice
    const int wn   = warp & 3;    // 0..3 -> 16-col slice

    if (t < GBM) { sS[t] = 0.0f; sD[t] = 0.0f; }

    float acc[2][2][4];
#pragma unroll
    for (int mt = 0; mt < 2; mt++)
#pragma unroll
        for (int nt = 0; nt < 2; nt++)
#pragma unroll
            for (int i = 0; i < 4; i++) acc[mt][nt][i] = 0.0f;

    const int arow = t >> 3;          // 0..31
    const int acol = (t & 7) * 4;     // float offset within BK

    uint32_t asA[2][2], asB[2][2];
#pragma unroll
    for (int bufi = 0; bufi < 2; bufi++) {
#pragma unroll
        for (int j = 0; j < 2; j++) {
            asA[bufi][j] = (uint32_t)__cvta_generic_to_shared(&As[bufi][arow + 32 * j][acol]);
            asB[bufi][j] = (uint32_t)__cvta_generic_to_shared(&Bs[bufi][arow + 32 * j][acol]);
        }
    }

    // prologue: stage tile 0
#pragma unroll
    for (int j = 0; j < 2; j++) {
        cp16(asA[0][j], &x[(bm + arow + 32 * j) * INF_ + acol]);
        cp16(asB[0][j], &W[(bo + arow + 32 * j) * INF_ + acol]);
    }
    cp_commit();

#pragma unroll
    for (int kt = 0; kt < KITERS; kt++) {
        const int cur = kt & 1;
        const int nxt = cur ^ 1;

        cp_wait_all();
        __syncthreads();

        if (kt + 1 < KITERS) {
            const int k0 = (kt + 1) * GBK;
#pragma unroll
            for (int j = 0; j < 2; j++) {
                cp16(asA[nxt][j], &x[(bm + arow + 32 * j) * INF_ + k0 + acol]);
                cp16(asB[nxt][j], &W[(bo + arow + 32 * j) * INF_ + k0 + acol]);
            }
            cp_commit();
        }

#pragma unroll
        for (int ks = 0; ks < 4; ks++) {
            const int kc = ks * 8 + (lane & 3);
            uint32_t Af[2][4];
#pragma unroll
            for (int mt = 0; mt < 2; mt++) {
                const int r0 = wm * 32 + mt * 16 + (lane >> 2);
                Af[mt][0] = tf32_rna(As[cur][r0][kc]);
                Af[mt][1] = tf32_rna(As[cur][r0 + 8][kc]);
                Af[mt][2] = tf32_rna(As[cur][r0][kc + 4]);
                Af[mt][3] = tf32_rna(As[cur][r0 + 8][kc + 4]);
            }
            uint32_t Bf[2][2];
#pragma unroll
            for (int nt = 0; nt < 2; nt++) {
                const int n0 = wn * 16 + nt * 8 + (lane >> 2);
                Bf[nt][0] = tf32_rna(Bs[cur][n0][kc]);
                Bf[nt][1] = tf32_rna(Bs[cur][n0][kc + 4]);
            }
#pragma unroll
            for (int mt = 0; mt < 2; mt++)
#pragma unroll
                for (int nt = 0; nt < 2; nt++)
                    mma_tf32(acc[mt][nt], Af[mt][0], Af[mt][1], Af[mt][2], Af[mt][3],
                             Bf[nt][0], Bf[nt][1]);
        }
    }

    // ---- epilogue A: fp16 h stores
#pragma unroll
    for (int mt = 0; mt < 2; mt++) {
#pragma unroll
        for (int nt = 0; nt < 2; nt++) {
            const int row = bm + wm * 32 + mt * 16 + (lane >> 2);
            const int col = bo + wn * 16 + nt * 8 + (lane & 3) * 2;
            float2 v0 = make_float2(acc[mt][nt][0], acc[mt][nt][1]);
            float2 v1 = make_float2(acc[mt][nt][2], acc[mt][nt][3]);
            *reinterpret_cast<__half2*>(&g_h16[row * HF_ + col]) = __float22half2_rn(v0);
            *reinterpret_cast<__half2*>(&g_h16[(row + 8) * HF_ + col]) = __float22half2_rn(v1);
        }
    }

    // ---- epilogue B: fused s_src/s_dst for this head
    float asv[2][2], adv[2][2];
#pragma unroll
    for (int nt = 0; nt < 2; nt++)
#pragma unroll
        for (int j = 0; j < 2; j++) {
            const int c = wn * 16 + nt * 8 + (lane & 3) * 2 + j;
            asv[nt][j] = a_src[head * F_ + c];
            adv[nt][j] = a_dst[head * F_ + c];
        }

    __syncthreads();
#pragma unroll
    for (int mt = 0; mt < 2; mt++) {
        float ps0 = 0.f, ps1 = 0.f, pd0 = 0.f, pd1 = 0.f;
#pragma unroll
        for (int nt = 0; nt < 2; nt++) {
            ps0 = fmaf(acc[mt][nt][0], asv[nt][0], ps0);
            ps0 = fmaf(acc[mt][nt][1], asv[nt][1], ps0);
            ps1 = fmaf(acc[mt][nt][2], asv[nt][0], ps1);
            ps1 = fmaf(acc[mt][nt][3], asv[nt][1], ps1);
            pd0 = fmaf(acc[mt][nt][0], adv[nt][0], pd0);
            pd0 = fmaf(acc[mt][nt][1], adv[nt][1], pd0);
            pd1 = fmaf(acc[mt][nt][2], adv[nt][0], pd1);
            pd1 = fmaf(acc[mt][nt][3], adv[nt][1], pd1);
        }
#pragma unroll
        for (int o = 1; o < 4; o <<= 1) {
            ps0 += __shfl_xor_sync(0xFFFFFFFFu, ps0, o);
            ps1 += __shfl_xor_sync(0xFFFFFFFFu, ps1, o);
            pd0 += __shfl_xor_sync(0xFFFFFFFFu, pd0, o);
            pd1 += __shfl_xor_sync(0xFFFFFFFFu, pd1, o);
        }
        if ((lane & 3) == 0) {
            const int r = wm * 32 + mt * 16 + (lane >> 2);
            atomicAdd(&sS[r], ps0);
            atomicAdd(&sS[r + 8], ps1);
            atomicAdd(&sD[r], pd0);
            atomicAdd(&sD[r + 8], pd1);
        }
    }
    __syncthreads();
    if (t < GBM) {
        g_ssrc[(bm + t) * H_ + head] = sS[t];
        g_sdst[(bm + t) * H_ + head] = sD[t];
    }
}

// ---------------------------------------------------------------------------
__device__ __forceinline__ void accum_row(float2& a0, float2& a1, float2& a2, float2& a3,
                                          float p, const uint4& v)
{
    float2 f;
    f = __half22float2(*reinterpret_cast<const __half2*>(&v.x));
    a0.x = fmaf(p, f.x, a0.x); a0.y = fmaf(p, f.y, a0.y);
    f = __half22float2(*reinterpret_cast<const __half2*>(&v.y));
    a1.x = fmaf(p, f.x, a1.x); a1.y = fmaf(p, f.y, a1.y);
    f = __half22float2(*reinterpret_cast<const __half2*>(&v.z));
    a2.x = fmaf(p, f.x, a2.x); a2.y = fmaf(p, f.y, a2.y);
    f = __half22float2(*reinterpret_cast<const __half2*>(&v.w));
    a3.x = fmaf(p, f.x, a3.x); a3.y = fmaf(p, f.y, a3.y);
}

// ---------------------------------------------------------------------------
// Kernel 2 (attn, exact R12/R9 form — measured best 32.8us; L2-BW-bound).
// ---------------------------------------------------------------------------
#define ATT_NPB 2   // n's per block; 4 warps = {b0,b1} x {n0,n1}

__global__ __launch_bounds__(128, 10) void attn_kernel(float* __restrict__ out)
{
    __shared__ __align__(16) int   nbS[ATT_NPB][MAXD_S];
    __shared__ __align__(16) float pS[4][H_ * PSTR];
    __shared__ int degS[ATT_NPB];

    const int t    = threadIdx.x;
    const int w    = t >> 5;
    const int lane = t & 31;
    const int b    = w & 1;
    const int nsub = w >> 1;
    const int n    = blockIdx.x * ATT_NPB + nsub;
    const int bn   = b * N_ + n;

    if (b == 0) {
        if (lane == 0) degS[nsub] = g_deg[n];
        const int dg = g_deg[n];
        for (int i = lane; i < dg && i < MAXD_S; i += 32)
            nbS[nsub][i] = g_nbrs[n * MAXD + i];
    }
    __syncthreads();

    const int deg  = degS[nsub];
    const int degc = deg < MAXD_S ? deg : MAXD_S;
    const int bN   = b * N_;

    const float4 c4 = *reinterpret_cast<const float4*>(&g_ssrc[bn * H_]);
    const float4* __restrict__ sd4 = reinterpret_cast<const float4*>(g_sdst);

    // ---- phase 1: strided p computation (all heads), padded head-major smem
    float4 sum4 = make_float4(0.f, 0.f, 0.f, 0.f);
    for (int i = lane; i < degc; i += 32) {
        const int m = nbS[nsub][i];
        float4 sdv = sd4[bN + m];
        float ex = c4.x + sdv.x, ey = c4.y + sdv.y, ez = c4.z + sdv.z, ew = c4.w + sdv.w;
        ex = fmaxf(ex, 0.2f * ex);
        ey = fmaxf(ey, 0.2f * ey);
        ez = fmaxf(ez, 0.2f * ez);
        ew = fmaxf(ew, 0.2f * ew);
        float px = __expf(ex), py = __expf(ey), pz = __expf(ez), pw = __expf(ew);
        pS[w][0 * PSTR + i] = px;
        pS[w][1 * PSTR + i] = py;
        pS[w][2 * PSTR + i] = pz;
        pS[w][3 * PSTR + i] = pw;
        sum4.x += px; sum4.y += py; sum4.z += pz; sum4.w += pw;
    }
    for (int i = degc + lane; i < deg; i += 32) {
        const int m = g_nbrs[n * MAXD + i];
        float4 sdv = sd4[bN + m];
        float ex = c4.x + sdv.x, ey = c4.y + sdv.y, ez = c4.z + sdv.z, ew = c4.w + sdv.w;
        ex = fmaxf(ex, 0.2f * ex);
        ey = fmaxf(ey, 0.2f * ey);
        ez = fmaxf(ez, 0.2f * ez);
        ew = fmaxf(ew, 0.2f * ew);
        sum4.x += __expf(ex); sum4.y += __expf(ey); sum4.z += __expf(ez); sum4.w += __expf(ew);
    }
#pragma unroll
    for (int o = 16; o > 0; o >>= 1) {
        sum4.x += __shfl_xor_sync(0xFFFFFFFFu, sum4.x, o);
        sum4.y += __shfl_xor_sync(0xFFFFFFFFu, sum4.y, o);
        sum4.z += __shfl_xor_sync(0xFFFFFFFFu, sum4.z, o);
        sum4.w += __shfl_xor_sync(0xFFFFFFFFu, sum4.w, o);
    }

    const int head = lane >> 3;
    float invh = (head & 2) ? ((head & 1) ? sum4.w : sum4.z)
                            : ((head & 1) ? sum4.y : sum4.x);
    invh = 1.0f / invh;

    __syncwarp();

    // ---- phase 2: gather + weighted accumulate, unrolled x4 (MLP 4)
    const uint4* __restrict__ hrow = reinterpret_cast<const uint4*>(g_h16) + (long long)bN * 32 + lane;
    const float* __restrict__ pw = &pS[w][head * PSTR];
    const int*   __restrict__ nbp = &nbS[nsub][0];

    float2 a0 = make_float2(0.f, 0.f), a1 = a0, a2 = a0, a3 = a0;

    int i = 0;
    for (; i + 4 <= degc; i += 4) {
        const int4   mm = *reinterpret_cast<const int4*>(&nbp[i]);
        const float4 pp = *reinterpret_cast<const float4*>(&pw[i]);
        const uint4 v0 = hrow[mm.x * 32];
        const uint4 v1 = hrow[mm.y * 32];
        const uint4 v2 = hrow[mm.z * 32];
        const uint4 v3 = hrow[mm.w * 32];
        accum_row(a0, a1, a2, a3, pp.x, v0);
        accum_row(a0, a1, a2, a3, pp.y, v1);
        accum_row(a0, a1, a2, a3, pp.z, v2);
        accum_row(a0, a1, a2, a3, pp.w, v3);
    }
    for (; i < degc; i++) {
        const float p0 = pw[i];
        const uint4 v0 = hrow[nbp[i] * 32];
        accum_row(a0, a1, a2, a3, p0, v0);
    }
    // tail beyond smem capacity: recompute p on the fly (statistically never)
    for (i = degc; i < deg; i++) {
        const int m0 = g_nbrs[n * MAXD + i];
        float4 sdv = sd4[bN + m0];
        float e = ((head & 2) ? ((head & 1) ? c4.w + sdv.w : c4.z + sdv.z)
                              : ((head & 1) ? c4.y + sdv.y : c4.x + sdv.x));
        e = fmaxf(e, 0.2f * e);
        const float p0 = __expf(e);
        const uint4 v0 = hrow[m0 * 32];
        accum_row(a0, a1, a2, a3, p0, v0);
    }

    float4 o0 = make_float4(a0.x * invh, a0.y * invh, a1.x * invh, a1.y * invh);
    float4 o1 = make_float4(a2.x * invh, a2.y * invh, a3.x * invh, a3.y * invh);
    float4* outp = reinterpret_cast<float4*>(out);
    outp[bn * 64 + lane * 2 + 0] = o0;
    outp[bn * 64 + lane * 2 + 1] = o1;
}

// ---------------------------------------------------------------------------
extern "C" void kernel_launch(void* const* d_in, const int* in_sizes, int n_in,
                              void* d_out, int out_size)
{
    const float* x     = (const float*)d_in[0];
    const float* adj   = (const float*)d_in[1];
    const float* W     = (const float*)d_in[2];
    const float* a_src = (const float*)d_in[3];
    const float* a_dst = (const float*)d_in[4];
    float* out = (float*)d_out;

    fused_gemm_csr<<<GEMM_BLOCKS + CSR_BLOCKS, 256>>>(x, W, a_src, a_dst, adj);
    attn_kernel<<<N_ / ATT_NPB, 128>>>(out);
}

// round 16
// speedup vs baseline: 1.2333x; 1.0173x over previous
#include <cuda_runtime.h>
#include <cuda_bf16.h>
#include <cuda_fp16.h>
#include <cstdint>

#define B_   2
#define N_   4096
#define INF_ 256
#define H_   4
#define F_   64
#define BN_  (B_ * N_)      // 8192
#define HF_  (H_ * F_)      // 256
#define MAXD   512
#define MAXD_S 128          // smem capacity (deg mean ~82, P(>128)~1e-7; tail fallback correct)
#define PSTR   (MAXD_S + 4) // 132: bank-shift -> conflict-free float4 LDS

#define GEMM_BLOCKS 512     // (BN_/GBM=64) * (HF_/GBN) = 128*4
#define CSR_BLOCKS  (N_ / 2)  // 2 adjacency rows per block

// ---------------- scratch (device globals) ----------------------------------
__device__ __align__(16) __half g_h16[BN_ * HF_];
__device__ __align__(16) float  g_ssrc[BN_ * H_];
__device__ __align__(16) float  g_sdst[BN_ * H_];
__device__ int g_nbrs[N_ * MAXD];
__device__ int g_deg[N_];

// ---------------------------------------------------------------------------
__device__ __forceinline__ uint32_t tf32_rna(float a) {
    uint32_t u;
    asm("cvt.rna.tf32.f32 %0, %1;" : "=r"(u) : "f"(a));
    return u;
}

__device__ __forceinline__ void mma_tf32(float c[4],
                                         uint32_t a0, uint32_t a1, uint32_t a2, uint32_t a3,
                                         uint32_t b0, uint32_t b1)
{
    asm volatile(
        "mma.sync.aligned.m16n8k8.row.col.f32.tf32.tf32.f32 "
        "{%0,%1,%2,%3},{%4,%5,%6,%7},{%8,%9},{%0,%1,%2,%3};"
        : "+f"(c[0]), "+f"(c[1]), "+f"(c[2]), "+f"(c[3])
        : "r"(a0), "r"(a1), "r"(a2), "r"(a3), "r"(b0), "r"(b1));
}

__device__ __forceinline__ void cp16(uint32_t dst_smem, const void* src) {
    asm volatile("cp.async.cg.shared.global [%0], [%1], 16;" :: "r"(dst_smem), "l"(src));
}
__device__ __forceinline__ void cp_commit() {
    asm volatile("cp.async.commit_group;");
}
__device__ __forceinline__ void cp_wait_all() {
    asm volatile("cp.async.wait_group 0;");
}

// ---------------------------------------------------------------------------
// Kernel 1 (fused, exact R15 form): blocks [0,512) = TF32 GEMM 64x64 tiles;
// blocks [512,512+2048) = adjacency scan (MLP-8, plain smem atomics).
// ---------------------------------------------------------------------------
#define GBM 64
#define GBN 64
#define GBK 32
#define GPAD 36
#define KITERS (INF_ / GBK)   // 8

__global__ __launch_bounds__(256, 4) void fused_gemm_csr(const float* __restrict__ x,
                                                         const float* __restrict__ W,
                                                         const float* __restrict__ a_src,
                                                         const float* __restrict__ a_dst,
                                                         const float* __restrict__ adj)
{
    __shared__ __align__(16) float As[2][GBM][GPAD];
    __shared__ __align__(16) float Bs[2][GBN][GPAD];
    __shared__ float sS[GBM], sD[GBM];
    __shared__ int cnt[2];

    const int bid = blockIdx.x;
    const int t   = threadIdx.x;

    // ================= CSR path: 2 rows per block =================
    if (bid >= GEMM_BLOCKS) {
        const int n0 = (bid - GEMM_BLOCKS) * 2;
        if (t < 2) cnt[t] = 0;
        __syncthreads();

        const int r  = t >> 7;
        const int tt = t & 127;
        const int n  = n0 + r;
        const float4* row4 = reinterpret_cast<const float4*>(adj + (long long)n * N_);

        float4 v[8];
#pragma unroll
        for (int j = 0; j < 8; j++)
            v[j] = row4[tt + 128 * j];

#pragma unroll
        for (int j = 0; j < 8; j++) {
            const int base = (tt + 128 * j) * 4;
            if (v[j].x != 0.0f) { int p = atomicAdd(&cnt[r], 1); if (p < MAXD) g_nbrs[n * MAXD + p] = base + 0; }
            if (v[j].y != 0.0f) { int p = atomicAdd(&cnt[r], 1); if (p < MAXD) g_nbrs[n * MAXD + p] = base + 1; }
            if (v[j].z != 0.0f) { int p = atomicAdd(&cnt[r], 1); if (p < MAXD) g_nbrs[n * MAXD + p] = base + 2; }
            if (v[j].w != 0.0f) { int p = atomicAdd(&cnt[r], 1); if (p < MAXD) g_nbrs[n * MAXD + p] = base + 3; }
        }
        __syncthreads();
        if (t < 2) g_deg[n0 + t] = cnt[t] < MAXD ? cnt[t] : MAXD;
        return;
    }

    // ================= GEMM path: 64x64 tile, 8 warps = 2(m) x 4(n) =========
    const int head = bid & 3;
    const int bm   = (bid >> 2) * GBM;
    const int bo   = head * GBN;

    const int lane = t & 31;
    const int warp = t >> 5;
    const int wm   = warp >> 2;
    const int wn   = warp & 3;

    if (t < GBM) { sS[t] = 0.0f; sD[t] = 0.0f; }

    float acc[2][2][4];
#pragma unroll
    for (int mt = 0; mt < 2; mt++)
#pragma unroll
        for (int nt = 0; nt < 2; nt++)
#pragma unroll
            for (int i = 0; i < 4; i++) acc[mt][nt][i] = 0.0f;

    const int arow = t >> 3;
    const int acol = (t & 7) * 4;

    uint32_t asA[2][2], asB[2][2];
#pragma unroll
    for (int bufi = 0; bufi < 2; bufi++) {
#pragma unroll
        for (int j = 0; j < 2; j++) {
            asA[bufi][j] = (uint32_t)__cvta_generic_to_shared(&As[bufi][arow + 32 * j][acol]);
            asB[bufi][j] = (uint32_t)__cvta_generic_to_shared(&Bs[bufi][arow + 32 * j][acol]);
        }
    }

#pragma unroll
    for (int j = 0; j < 2; j++) {
        cp16(asA[0][j], &x[(bm + arow + 32 * j) * INF_ + acol]);
        cp16(asB[0][j], &W[(bo + arow + 32 * j) * INF_ + acol]);
    }
    cp_commit();

#pragma unroll
    for (int kt = 0; kt < KITERS; kt++) {
        const int cur = kt & 1;
        const int nxt = cur ^ 1;

        cp_wait_all();
        __syncthreads();

        if (kt + 1 < KITERS) {
            const int k0 = (kt + 1) * GBK;
#pragma unroll
            for (int j = 0; j < 2; j++) {
                cp16(asA[nxt][j], &x[(bm + arow + 32 * j) * INF_ + k0 + acol]);
                cp16(asB[nxt][j], &W[(bo + arow + 32 * j) * INF_ + k0 + acol]);
            }
            cp_commit();
        }

#pragma unroll
        for (int ks = 0; ks < 4; ks++) {
            const int kc = ks * 8 + (lane & 3);
            uint32_t Af[2][4];
#pragma unroll
            for (int mt = 0; mt < 2; mt++) {
                const int r0 = wm * 32 + mt * 16 + (lane >> 2);
                Af[mt][0] = tf32_rna(As[cur][r0][kc]);
                Af[mt][1] = tf32_rna(As[cur][r0 + 8][kc]);
                Af[mt][2] = tf32_rna(As[cur][r0][kc + 4]);
                Af[mt][3] = tf32_rna(As[cur][r0 + 8][kc + 4]);
            }
            uint32_t Bf[2][2];
#pragma unroll
            for (int nt = 0; nt < 2; nt++) {
                const int n0 = wn * 16 + nt * 8 + (lane >> 2);
                Bf[nt][0] = tf32_rna(Bs[cur][n0][kc]);
                Bf[nt][1] = tf32_rna(Bs[cur][n0][kc + 4]);
            }
#pragma unroll
            for (int mt = 0; mt < 2; mt++)
#pragma unroll
                for (int nt = 0; nt < 2; nt++)
                    mma_tf32(acc[mt][nt], Af[mt][0], Af[mt][1], Af[mt][2], Af[mt][3],
                             Bf[nt][0], Bf[nt][1]);
        }
    }

#pragma unroll
    for (int mt = 0; mt < 2; mt++) {
#pragma unroll
        for (int nt = 0; nt < 2; nt++) {
            const int row = bm + wm * 32 + mt * 16 + (lane >> 2);
            const int col = bo + wn * 16 + nt * 8 + (lane & 3) * 2;
            float2 v0 = make_float2(acc[mt][nt][0], acc[mt][nt][1]);
            float2 v1 = make_float2(acc[mt][nt][2], acc[mt][nt][3]);
            *reinterpret_cast<__half2*>(&g_h16[row * HF_ + col]) = __float22half2_rn(v0);
            *reinterpret_cast<__half2*>(&g_h16[(row + 8) * HF_ + col]) = __float22half2_rn(v1);
        }
    }

    float asv[2][2], adv[2][2];
#pragma unroll
    for (int nt = 0; nt < 2; nt++)
#pragma unroll
        for (int j = 0; j < 2; j++) {
            const int c = wn * 16 + nt * 8 + (lane & 3) * 2 + j;
            asv[nt][j] = a_src[head * F_ + c];
            adv[nt][j] = a_dst[head * F_ + c];
        }

    __syncthreads();
#pragma unroll
    for (int mt = 0; mt < 2; mt++) {
        float ps0 = 0.f, ps1 = 0.f, pd0 = 0.f, pd1 = 0.f;
#pragma unroll
        for (int nt = 0; nt < 2; nt++) {
            ps0 = fmaf(acc[mt][nt][0], asv[nt][0], ps0);
            ps0 = fmaf(acc[mt][nt][1], asv[nt][1], ps0);
            ps1 = fmaf(acc[mt][nt][2], asv[nt][0], ps1);
            ps1 = fmaf(acc[mt][nt][3], asv[nt][1], ps1);
            pd0 = fmaf(acc[mt][nt][0], adv[nt][0], pd0);
            pd0 = fmaf(acc[mt][nt][1], adv[nt][1], pd0);
            pd1 = fmaf(acc[mt][nt][2], adv[nt][0], pd1);
            pd1 = fmaf(acc[mt][nt][3], adv[nt][1], pd1);
        }
#pragma unroll
        for (int o = 1; o < 4; o <<= 1) {
            ps0 += __shfl_xor_sync(0xFFFFFFFFu, ps0, o);
            ps1 += __shfl_xor_sync(0xFFFFFFFFu, ps1, o);
            pd0 += __shfl_xor_sync(0xFFFFFFFFu, pd0, o);
            pd1 += __shfl_xor_sync(0xFFFFFFFFu, pd1, o);
        }
        if ((lane & 3) == 0) {
            const int r = wm * 32 + mt * 16 + (lane >> 2);
            atomicAdd(&sS[r], ps0);
            atomicAdd(&sS[r + 8], ps1);
            atomicAdd(&sD[r], pd0);
            atomicAdd(&sD[r + 8], pd1);
        }
    }
    __syncthreads();
    if (t < GBM) {
        g_ssrc[(bm + t) * H_ + head] = sS[t];
        g_sdst[(bm + t) * H_ + head] = sD[t];
    }
}

// ---------------------------------------------------------------------------
// packed-f32x2 accumulate: 4 FFMA2 instead of 8 FFMA per gathered row.
// Per-element operation order identical to scalar version -> same numerics.
// ---------------------------------------------------------------------------
__device__ __forceinline__ void accum_row2(unsigned long long& a0, unsigned long long& a1,
                                           unsigned long long& a2, unsigned long long& a3,
                                           unsigned long long pd, const uint4& v)
{
    float2 f;
    unsigned long long g;
    f = __half22float2(*reinterpret_cast<const __half2*>(&v.x));
    asm("mov.b64 %0,{%1,%2};" : "=l"(g) : "f"(f.x), "f"(f.y));
    asm("fma.rn.f32x2 %0, %1, %2, %0;" : "+l"(a0) : "l"(g), "l"(pd));
    f = __half22float2(*reinterpret_cast<const __half2*>(&v.y));
    asm("mov.b64 %0,{%1,%2};" : "=l"(g) : "f"(f.x), "f"(f.y));
    asm("fma.rn.f32x2 %0, %1, %2, %0;" : "+l"(a1) : "l"(g), "l"(pd));
    f = __half22float2(*reinterpret_cast<const __half2*>(&v.z));
    asm("mov.b64 %0,{%1,%2};" : "=l"(g) : "f"(f.x), "f"(f.y));
    asm("fma.rn.f32x2 %0, %1, %2, %0;" : "+l"(a2) : "l"(g), "l"(pd));
    f = __half22float2(*reinterpret_cast<const __half2*>(&v.w));
    asm("mov.b64 %0,{%1,%2};" : "=l"(g) : "f"(f.x), "f"(f.y));
    asm("fma.rn.f32x2 %0, %1, %2, %0;" : "+l"(a3) : "l"(g), "l"(pd));
}

__device__ __forceinline__ unsigned long long dup_f32x2(float p) {
    unsigned long long d;
    asm("mov.b64 %0,{%1,%1};" : "=l"(d) : "f"(p));
    return d;
}

// ---------------------------------------------------------------------------
// Kernel 2 (attn): R15 structure; gather accumulation via packed FFMA2.
// ---------------------------------------------------------------------------
#define ATT_NPB 2   // n's per block; 4 warps = {b0,b1} x {n0,n1}

__global__ __launch_bounds__(128, 10) void attn_kernel(float* __restrict__ out)
{
    __shared__ __align__(16) int   nbS[ATT_NPB][MAXD_S];
    __shared__ __align__(16) float pS[4][H_ * PSTR];
    __shared__ int degS[ATT_NPB];

    const int t    = threadIdx.x;
    const int w    = t >> 5;
    const int lane = t & 31;
    const int b    = w & 1;
    const int nsub = w >> 1;
    const int n    = blockIdx.x * ATT_NPB + nsub;
    const int bn   = b * N_ + n;

    if (b == 0) {
        if (lane == 0) degS[nsub] = g_deg[n];
        const int dg = g_deg[n];
        for (int i = lane; i < dg && i < MAXD_S; i += 32)
            nbS[nsub][i] = g_nbrs[n * MAXD + i];
    }
    __syncthreads();

    const int deg  = degS[nsub];
    const int degc = deg < MAXD_S ? deg : MAXD_S;
    const int bN   = b * N_;

    const float4 c4 = *reinterpret_cast<const float4*>(&g_ssrc[bn * H_]);
    const float4* __restrict__ sd4 = reinterpret_cast<const float4*>(g_sdst);

    // ---- phase 1: strided p computation (all heads), padded head-major smem
    float4 sum4 = make_float4(0.f, 0.f, 0.f, 0.f);
    for (int i = lane; i < degc; i += 32) {
        const int m = nbS[nsub][i];
        float4 sdv = sd4[bN + m];
        float ex = c4.x + sdv.x, ey = c4.y + sdv.y, ez = c4.z + sdv.z, ew = c4.w + sdv.w;
        ex = fmaxf(ex, 0.2f * ex);
        ey = fmaxf(ey, 0.2f * ey);
        ez = fmaxf(ez, 0.2f * ez);
        ew = fmaxf(ew, 0.2f * ew);
        float px = __expf(ex), py = __expf(ey), pz = __expf(ez), pw = __expf(ew);
        pS[w][0 * PSTR + i] = px;
        pS[w][1 * PSTR + i] = py;
        pS[w][2 * PSTR + i] = pz;
        pS[w][3 * PSTR + i] = pw;
        sum4.x += px; sum4.y += py; sum4.z += pz; sum4.w += pw;
    }
    for (int i = degc + lane; i < deg; i += 32) {
        const int m = g_nbrs[n * MAXD + i];
        float4 sdv = sd4[bN + m];
        float ex = c4.x + sdv.x, ey = c4.y + sdv.y, ez = c4.z + sdv.z, ew = c4.w + sdv.w;
        ex = fmaxf(ex, 0.2f * ex);
        ey = fmaxf(ey, 0.2f * ey);
        ez = fmaxf(ez, 0.2f * ez);
        ew = fmaxf(ew, 0.2f * ew);
        sum4.x += __expf(ex); sum4.y += __expf(ey); sum4.z += __expf(ez); sum4.w += __expf(ew);
    }
#pragma unroll
    for (int o = 16; o > 0; o >>= 1) {
        sum4.x += __shfl_xor_sync(0xFFFFFFFFu, sum4.x, o);
        sum4.y += __shfl_xor_sync(0xFFFFFFFFu, sum4.y, o);
        sum4.z += __shfl_xor_sync(0xFFFFFFFFu, sum4.z, o);
        sum4.w += __shfl_xor_sync(0xFFFFFFFFu, sum4.w, o);
    }

    const int head = lane >> 3;
    float invh = (head & 2) ? ((head & 1) ? sum4.w : sum4.z)
                            : ((head & 1) ? sum4.y : sum4.x);
    invh = 1.0f / invh;

    __syncwarp();

    // ---- phase 2: gather + packed-FFMA2 accumulate, unrolled x4 (MLP 4)
    const uint4* __restrict__ hrow = reinterpret_cast<const uint4*>(g_h16) + (long long)bN * 32 + lane;
    const float* __restrict__ pw = &pS[w][head * PSTR];
    const int*   __restrict__ nbp = &nbS[nsub][0];

    unsigned long long a0 = 0ull, a1 = 0ull, a2 = 0ull, a3 = 0ull;  // f32x2 accumulators (0.0,0.0)

    int i = 0;
    for (; i + 4 <= degc; i += 4) {
        const int4   mm = *reinterpret_cast<const int4*>(&nbp[i]);
        const float4 pp = *reinterpret_cast<const float4*>(&pw[i]);
        const uint4 v0 = hrow[mm.x * 32];
        const uint4 v1 = hrow[mm.y * 32];
        const uint4 v2 = hrow[mm.z * 32];
        const uint4 v3 = hrow[mm.w * 32];
        accum_row2(a0, a1, a2, a3, dup_f32x2(pp.x), v0);
        accum_row2(a0, a1, a2, a3, dup_f32x2(pp.y), v1);
        accum_row2(a0, a1, a2, a3, dup_f32x2(pp.z), v2);
        accum_row2(a0, a1, a2, a3, dup_f32x2(pp.w), v3);
    }
    for (; i < degc; i++) {
        const uint4 v0 = hrow[nbp[i] * 32];
        accum_row2(a0, a1, a2, a3, dup_f32x2(pw[i]), v0);
    }
    // tail beyond smem capacity: recompute p on the fly (statistically never)
    for (i = degc; i < deg; i++) {
        const int m0 = g_nbrs[n * MAXD + i];
        float4 sdv = sd4[bN + m0];
        float e = ((head & 2) ? ((head & 1) ? c4.w + sdv.w : c4.z + sdv.z)
                              : ((head & 1) ? c4.y + sdv.y : c4.x + sdv.x));
        e = fmaxf(e, 0.2f * e);
        const uint4 v0 = hrow[m0 * 32];
        accum_row2(a0, a1, a2, a3, dup_f32x2(__expf(e)), v0);
    }

    float2 f0, f1, f2, f3;
    asm("mov.b64 {%0,%1}, %2;" : "=f"(f0.x), "=f"(f0.y) : "l"(a0));
    asm("mov.b64 {%0,%1}, %2;" : "=f"(f1.x), "=f"(f1.y) : "l"(a1));
    asm("mov.b64 {%0,%1}, %2;" : "=f"(f2.x), "=f"(f2.y) : "l"(a2));
    asm("mov.b64 {%0,%1}, %2;" : "=f"(f3.x), "=f"(f3.y) : "l"(a3));

    float4 o0 = make_float4(f0.x * invh, f0.y * invh, f1.x * invh, f1.y * invh);
    float4 o1 = make_float4(f2.x * invh, f2.y * invh, f3.x * invh, f3.y * invh);
    float4* outp = reinterpret_cast<float4*>(out);
    outp[bn * 64 + lane * 2 + 0] = o0;
    outp[bn * 64 + lane * 2 + 1] = o1;
}

// ---------------------------------------------------------------------------
extern "C" void kernel_launch(void* const* d_in, const int* in_sizes, int n_in,
                              void* d_out, int out_size)
{
    const float* x     = (const float*)d_in[0];
    const float* adj   = (const float*)d_in[1];
    const float* W     = (const float*)d_in[2];
    const float* a_src = (const float*)d_in[3];
    const float* a_dst = (const float*)d_in[4];
    float* out = (float*)d_out;

    fused_gemm_csr<<<GEMM_BLOCKS + CSR_BLOCKS, 256>>>(x, W, a_src, a_dst, adj);
    attn_kernel<<<N_ / ATT_NPB, 128>>>(out);
}